// round 1
// baseline (speedup 1.0000x reference)
#include <cuda_runtime.h>
#include <math.h>

#define FULLM 0xffffffffu
static const int NMAX = 100352;
static const int EMAX = 1700000;

// ---------------- device scratch (static: no allocation allowed) ----------------
__device__ int      d_is64;
__device__ int      d_cnt[NMAX];
__device__ int      d_cur[NMAX];
__device__ int      d_off[NMAX + 1];
__device__ float    d_dinv[NMAX];
__device__ int      d_col[EMAX];
__device__ unsigned d_bits0[NMAX * 8];
__device__ unsigned d_bits1[NMAX * 4];
__device__ unsigned d_bits2[NMAX * 4];
__device__ __align__(16) float d_g[NMAX * 128];
__device__ float    d_mu[256];
__device__ float    d_part[512 * 256];
__device__ unsigned d_wb0[8 * 128];
__device__ unsigned d_wb1[4 * 128];
__device__ unsigned d_wb2[4 * 40];
__device__ float    d_al0[128];
__device__ float    d_al1[128];
__device__ float    d_al2[40];

// ---------------- edge dtype detection (int32 vs int64) ----------------
__global__ void k_detect(const void* e) {
    __shared__ int s;
    if (threadIdx.x == 0) s = 0;
    __syncthreads();
    const unsigned* w = (const unsigned*)e;
    int z = 0;
    for (int i = threadIdx.x; i < 1024; i += blockDim.x)
        if (w[2 * i + 1] == 0) z++;   // int64 positive values => high words all zero
    atomicAdd(&s, z);
    __syncthreads();
    if (threadIdx.x == 0) d_is64 = (s > 512);
}

__device__ __forceinline__ int ld_edge(const void* e, long long idx, int is64) {
    return is64 ? (int)((const long long*)e)[idx] : ((const int*)e)[idx];
}

__global__ void k_zero(int n) {
    int i = blockIdx.x * blockDim.x + threadIdx.x;
    if (i < n) { d_cnt[i] = 0; d_cur[i] = 0; }
}

// ---------------- deterministic column mean of x (N x 256) ----------------
__global__ void k_colsum_part(const float* __restrict__ x, int n) {
    int rows = (n + 511) / 512;
    int r0 = blockIdx.x * rows, r1 = min(n, r0 + rows);
    float s = 0.f;
    for (int r = r0; r < r1; r++) s += x[(long long)r * 256 + threadIdx.x];
    d_part[blockIdx.x * 256 + threadIdx.x] = s;
}

__global__ void k_colsum_fin(int n) {
    float s = 0.f;
    for (int b = 0; b < 512; b++) s += d_part[b * 256 + threadIdx.x];
    d_mu[threadIdx.x] = s / (float)n;
}

// ---------------- degree histogram over dst ----------------
__global__ void k_deg(const void* e, long long E) {
    long long i = (long long)blockIdx.x * blockDim.x + threadIdx.x;
    if (i < E) {
        int is64 = d_is64;
        int dd = ld_edge(e, E + i, is64);
        atomicAdd(&d_cnt[dd], 1);
    }
}

// ---------------- exclusive scan of counts -> CSR offsets; dinv = rsqrt(deg+1) ----------------
__global__ void k_scan(int n) {
    __shared__ int ss[1024];
    int tid = threadIdx.x;
    int chunk = (n + 1023) / 1024;
    int c0 = tid * chunk, c1 = min(n, c0 + chunk);
    int s = 0;
    for (int i = c0; i < c1; i++) s += d_cnt[i];
    ss[tid] = s;
    __syncthreads();
    for (int off = 1; off < 1024; off <<= 1) {
        int v = (tid >= off) ? ss[tid - off] : 0;
        __syncthreads();
        ss[tid] += v;
        __syncthreads();
    }
    int run = ss[tid] - s;   // exclusive prefix of this thread's chunk
    for (int i = c0; i < c1; i++) {
        d_off[i] = run;
        run += d_cnt[i];
        d_dinv[i] = rsqrtf((float)(d_cnt[i] + 1));   // +1: self loop
    }
    if (c0 < n && c1 == n) d_off[n] = run;
}

// ---------------- CSR fill (col = src per dst) ----------------
__global__ void k_csr(const void* e, long long E) {
    long long i = (long long)blockIdx.x * blockDim.x + threadIdx.x;
    if (i < E) {
        int is64 = d_is64;
        int sv = ld_edge(e, i, is64);
        int dv = ld_edge(e, E + i, is64);
        int pos = d_off[dv] + atomicAdd(&d_cur[dv], 1);
        d_col[pos] = sv;
    }
}

// ---------------- weight binarization: bits + alpha (one warp per out column) ----------------
__global__ void k_wprep(const float* __restrict__ W, int K, int OUT, int which) {
    unsigned* wbT = (which == 0) ? d_wb0 : (which == 1) ? d_wb1 : d_wb2;
    float* alpha = (which == 0) ? d_al0 : (which == 1) ? d_al1 : d_al2;
    int j = blockIdx.x, lane = threadIdx.x;
    float s = 0.f;
    int KW = K / 32;
    for (int w = 0; w < KW; w++) {
        float v = W[(long long)(w * 32 + lane) * OUT + j];
        s += fabsf(v);
        unsigned m = __ballot_sync(FULLM, v > 0.f);
        if (lane == 0) wbT[w * OUT + j] = m;
    }
    for (int o = 16; o; o >>= 1) s += __shfl_xor_sync(FULLM, s, o);
    if (lane == 0) alpha[j] = s / (float)K;
}

// ---------------- BN+sign fused: bits0 = (x > mu) packed, one warp per node ----------------
__global__ void k_bnpack(const float* __restrict__ x, int n) {
    __shared__ float smu[256];
    smu[threadIdx.x] = d_mu[threadIdx.x];
    __syncthreads();
    int warp = (blockIdx.x * blockDim.x + threadIdx.x) >> 5;
    int lane = threadIdx.x & 31;
    if (warp >= n) return;
    const float* xr = x + (long long)warp * 256;
#pragma unroll
    for (int w = 0; w < 8; w++) {
        float v = xr[w * 32 + lane];
        unsigned m = __ballot_sync(FULLM, v > smu[w * 32 + lane]);
        if (lane == w) d_bits0[warp * 8 + w] = m;
    }
}

// ---------------- binary matmul via XOR+popcount; epilogue bakes alpha and dinv ----------------
// g[n,j] = dinv[n] * alpha[j] * (K - 2*popc(a ^ w))
template <int KW, int OUT, int NL, int ITER, int LAYER>
__global__ void k_bmm(int n) {
    const unsigned* bits = (LAYER == 0) ? d_bits0 : (LAYER == 1) ? d_bits1 : d_bits2;
    const unsigned* wbT  = (LAYER == 0) ? d_wb0  : (LAYER == 1) ? d_wb1  : d_wb2;
    const float*    alp  = (LAYER == 0) ? d_al0  : (LAYER == 1) ? d_al1  : d_al2;
    int t = threadIdx.x;
    if (t >= NL * OUT) return;
    int j = t % OUT, nl = t / OUT;
    unsigned wr[KW];
#pragma unroll
    for (int w = 0; w < KW; w++) wr[w] = wbT[w * OUT + j];
    float aj = alp[j];
    int base = blockIdx.x * (NL * ITER) + nl;
#pragma unroll 4
    for (int it = 0; it < ITER; it++) {
        int nn = base + it * NL;
        if (nn >= n) break;
        const unsigned* ab = bits + (long long)nn * KW;
        int p = 0;
#pragma unroll
        for (int w = 0; w < KW; w++) p += __popc(ab[w] ^ wr[w]);
        d_g[(long long)nn * OUT + j] = (float)(KW * 32 - 2 * p) * aj * d_dinv[nn];
    }
}

// ---------------- aggregation (pull, 128 features) fused with bias+sign+bitpack ----------------
template <int OLAYER>
__global__ void k_agg_pack(const float* __restrict__ bias, int n) {
    unsigned* obits = (OLAYER == 1) ? d_bits1 : d_bits2;
    int wid = (blockIdx.x * blockDim.x + threadIdx.x) >> 5;
    int lane = threadIdx.x & 31;
    if (wid >= n) return;
    const float4* gp = (const float4*)d_g;
    float4 a0 = gp[(long long)wid * 32 + lane];   // self loop term g[d]
    float4 a1 = make_float4(0.f, 0.f, 0.f, 0.f);
    int k = d_off[wid], k1 = d_off[wid + 1];
    for (; k + 2 <= k1; k += 2) {
        int s0 = d_col[k], s1 = d_col[k + 1];
        float4 v0 = gp[(long long)s0 * 32 + lane];
        float4 v1 = gp[(long long)s1 * 32 + lane];
        a0.x += v0.x; a0.y += v0.y; a0.z += v0.z; a0.w += v0.w;
        a1.x += v1.x; a1.y += v1.y; a1.z += v1.z; a1.w += v1.w;
    }
    if (k < k1) {
        int s0 = d_col[k];
        float4 v0 = gp[(long long)s0 * 32 + lane];
        a0.x += v0.x; a0.y += v0.y; a0.z += v0.z; a0.w += v0.w;
    }
    float di = d_dinv[wid];
    float4 b = ((const float4*)bias)[lane];
    float v0 = (a0.x + a1.x) * di + b.x;
    float v1 = (a0.y + a1.y) * di + b.y;
    float v2 = (a0.z + a1.z) * di + b.z;
    float v3 = (a0.w + a1.w) * di + b.w;
    unsigned nib = (unsigned)(v0 > 0.f) | ((unsigned)(v1 > 0.f) << 1) |
                   ((unsigned)(v2 > 0.f) << 2) | ((unsigned)(v3 > 0.f) << 3);
    unsigned sh = nib << ((lane & 7) * 4);
    sh |= __shfl_xor_sync(FULLM, sh, 1);
    sh |= __shfl_xor_sync(FULLM, sh, 2);
    sh |= __shfl_xor_sync(FULLM, sh, 4);
    if ((lane & 7) == 0) obits[wid * 4 + (lane >> 3)] = sh;
}

// ---------------- final aggregation (40 features) fused with bias + log_softmax ----------------
__global__ void k_agg_out(const float* __restrict__ bias, float* __restrict__ out, int n) {
    int wid = (blockIdx.x * blockDim.x + threadIdx.x) >> 5;
    int lane = threadIdx.x & 31;
    if (wid >= n) return;
    const float2* gp = (const float2*)d_g;
    bool act = lane < 20;
    float2 a0 = make_float2(0.f, 0.f), a1 = make_float2(0.f, 0.f);
    if (act) a0 = gp[(long long)wid * 20 + lane];   // self loop
    int k = d_off[wid], k1 = d_off[wid + 1];
    for (; k + 2 <= k1; k += 2) {
        int s0 = d_col[k], s1 = d_col[k + 1];
        if (act) {
            float2 v0 = gp[(long long)s0 * 20 + lane];
            float2 v1 = gp[(long long)s1 * 20 + lane];
            a0.x += v0.x; a0.y += v0.y;
            a1.x += v1.x; a1.y += v1.y;
        }
    }
    if (k < k1) {
        int s0 = d_col[k];
        if (act) {
            float2 v0 = gp[(long long)s0 * 20 + lane];
            a0.x += v0.x; a0.y += v0.y;
        }
    }
    float di = d_dinv[wid];
    float v0 = -1e30f, v1 = -1e30f;
    if (act) {
        float2 b = ((const float2*)bias)[lane];
        v0 = (a0.x + a1.x) * di + b.x;
        v1 = (a0.y + a1.y) * di + b.y;
    }
    float m = fmaxf(v0, v1);
    for (int o = 16; o; o >>= 1) m = fmaxf(m, __shfl_xor_sync(FULLM, m, o));
    float se = act ? (expf(v0 - m) + expf(v1 - m)) : 0.f;
    for (int o = 16; o; o >>= 1) se += __shfl_xor_sync(FULLM, se, o);
    float lse = logf(se);
    if (act) {
        float2 r;
        r.x = v0 - m - lse;
        r.y = v1 - m - lse;
        ((float2*)out)[(long long)wid * 20 + lane] = r;
    }
}

// ---------------- launch ----------------
extern "C" void kernel_launch(void* const* d_in, const int* in_sizes, int n_in,
                              void* d_out, int out_size) {
    const float* x  = (const float*)d_in[0];
    const void*  ei = d_in[1];
    const float* W0 = (const float*)d_in[2];
    const float* b0 = (const float*)d_in[3];
    const float* W1 = (const float*)d_in[4];
    const float* b1 = (const float*)d_in[5];
    const float* W2 = (const float*)d_in[6];
    const float* b2 = (const float*)d_in[7];
    float* out = (float*)d_out;

    int N = in_sizes[0] / 256;
    long long E = (long long)in_sizes[1] / 2;

    int nb256 = (N + 255) / 256;
    int eb = (int)((E + 255) / 256);
    int wb = (N + 7) / 8;       // warp-per-node kernels, 256-thread blocks

    k_detect<<<1, 256>>>(ei);
    k_zero<<<nb256, 256>>>(N);
    k_colsum_part<<<512, 256>>>(x, N);
    k_colsum_fin<<<1, 256>>>(N);
    k_deg<<<eb, 256>>>(ei, E);
    k_scan<<<1, 1024>>>(N);
    k_csr<<<eb, 256>>>(ei, E);
    k_wprep<<<128, 32>>>(W0, 256, 128, 0);
    k_wprep<<<128, 32>>>(W1, 128, 128, 1);
    k_wprep<<<40, 32>>>(W2, 128, 40, 2);
    k_bnpack<<<wb, 256>>>(x, N);

    // layer 0: K=256 -> H=128
    k_bmm<8, 128, 1, 32, 0><<<(N + 31) / 32, 128>>>(N);
    k_agg_pack<1><<<wb, 256>>>(b0, N);
    // layer 1: K=128 -> H=128
    k_bmm<4, 128, 1, 32, 1><<<(N + 31) / 32, 128>>>(N);
    k_agg_pack<2><<<wb, 256>>>(b1, N);
    // layer 2: K=128 -> OUT=40, then aggregate + log_softmax
    k_bmm<4, 40, 3, 32, 2><<<(N + 95) / 96, 128>>>(N);
    k_agg_out<<<wb, 256>>>(b2, out, N);
}